// round 16
// baseline (speedup 1.0000x reference)
#include <cuda_runtime.h>
#include <math.h>
#include <stdint.h>

#define NMAX 16384
#define GMAX 1024
#define PI_F 3.14159265358979323846f

__device__ float g_node_f[NMAX * 2];
__device__ float g_eAB[NMAX * 2];
__device__ float g_upd[NMAX * 2];
__device__ float g_seg[GMAX * 2];
__device__ float g_cnt[GMAX];
__device__ int   g_ctr;

__device__ __forceinline__ float leaky(float x) { return x > 0.f ? x : 0.2f * x; }

__device__ __forceinline__ float ldcg(const float* p) {
    float v; asm volatile("ld.global.cg.f32 %0, [%1];" : "=f"(v) : "l"(p)); return v;
}

#define SHX(v, m) __shfl_xor_sync(0xffffffffu, (v), (m))

// ---------------- K1: 4 rows per warp, weights register-resident (R14 exact) -
__global__ void __launch_bounds__(128, 1)
k1_feat(const float* __restrict__ node_feat, int N,
        const float* __restrict__ edge_attr,
        const float* __restrict__ nW1, const float* __restrict__ nb1,
        const float* __restrict__ nW2, const float* __restrict__ nb2,
        const float* __restrict__ eW1, const float* __restrict__ eb1,
        const float* __restrict__ eW2, const float* __restrict__ eb2,
        const int* __restrict__ ge)
{
    int tid = threadIdx.x;
    int lane = tid & 31;
    int w = tid >> 5;
    int gtid = blockIdx.x * blockDim.x + tid;

    if (gtid < GMAX * 2) g_seg[gtid] = 0.f;
    else if (gtid < GMAX * 3) g_cnt[gtid - GMAX * 2] = 0.f;
    if (gtid == 0) g_ctr = 0;

    int j0 = 4 * lane;

    float wn[16][4];
#pragma unroll
    for (int k = 0; k < 16; k++) {
#pragma unroll
        for (int q = 0; q < 4; q++) wn[k][q] = __ldg(nW1 + k * 128 + j0 + q);
    }
    float bn[4], n2[4][2];
#pragma unroll
    for (int q = 0; q < 4; q++) {
        bn[q] = __ldg(nb1 + j0 + q);
        n2[q][0] = __ldg(nW2 + 2 * (j0 + q) + 0);
        n2[q][1] = __ldg(nW2 + 2 * (j0 + q) + 1);
    }
    float we[8][4];
#pragma unroll
    for (int k = 0; k < 8; k++) {
#pragma unroll
        for (int q = 0; q < 4; q++) we[k][q] = __ldg(eW1 + k * 128 + j0 + q);
    }
    float be[4], e2[4][2];
#pragma unroll
    for (int q = 0; q < 4; q++) {
        be[q] = __ldg(eb1 + j0 + q);
        e2[q][0] = __ldg(eW2 + 2 * (j0 + q) + 0);
        e2[q][1] = __ldg(eW2 + 2 * (j0 + q) + 1);
    }
    float nb2x = __ldg(nb2 + 0), nb2y = __ldg(nb2 + 1);
    float eb2x = __ldg(eb2 + 0), eb2y = __ldg(eb2 + 1);

    int warpId = blockIdx.x * (blockDim.x >> 5) + w;
    int base = warpId * 4;

#pragma unroll
    for (int rr = 0; rr < 4; rr++) {
        int row = base + rr;
        bool valid = row < N;
        int ic = min(row, N - 1);

        float x[16];
#pragma unroll
        for (int k = 0; k < 16; k++) x[k] = __ldg(node_feat + ic * 16 + k);

        float h[4] = {bn[0], bn[1], bn[2], bn[3]};
#pragma unroll
        for (int k = 0; k < 16; k++) {
#pragma unroll
            for (int q = 0; q < 4; q++) h[q] = fmaf(x[k], wn[k][q], h[q]);
        }
        float o0 = 0.f, o1 = 0.f;
#pragma unroll
        for (int q = 0; q < 4; q++) {
            float hq = leaky(h[q]);
            o0 = fmaf(hq, n2[q][0], o0);
            o1 = fmaf(hq, n2[q][1], o1);
        }

        int eidx = __ldg(ge + ic * 3);
        int ec = max(eidx, 0);
        float y[8];
#pragma unroll
        for (int k = 0; k < 8; k++) y[k] = __ldg(edge_attr + ec * 8 + k);

        float g[4] = {be[0], be[1], be[2], be[3]};
#pragma unroll
        for (int k = 0; k < 8; k++) {
#pragma unroll
            for (int q = 0; q < 4; q++) g[q] = fmaf(y[k], we[k][q], g[q]);
        }
        float p0 = 0.f, p1 = 0.f;
#pragma unroll
        for (int q = 0; q < 4; q++) {
            float gq = leaky(g[q]);
            p0 = fmaf(gq, e2[q][0], p0);
            p1 = fmaf(gq, e2[q][1], p1);
        }

#pragma unroll
        for (int off = 16; off >= 1; off >>= 1) {
            o0 += SHX(o0, off);
            o1 += SHX(o1, off);
            p0 += SHX(p0, off);
            p1 += SHX(p1, off);
        }

        if (lane == 0 && valid) {
            g_node_f[row * 2 + 0] = tanhf(o0 + nb2x) * PI_F;
            g_node_f[row * 2 + 1] = tanhf(o1 + nb2y) * PI_F;
            g_eAB[row * 2 + 0] = (eidx >= 0) ? tanhf(p0 + eb2x) * PI_F : 0.f;
            g_eAB[row * 2 + 1] = (eidx >= 0) ? tanhf(p1 + eb2y) * PI_F : 0.f;
        }
    }
}

// ---------------- K2: 16 threads/row, 2 rows per group (ILP=2); PDL ----------
// lane bits: q4 = sub&1 (mask 1), q7 = sub>>1 (mask 2), q8 = sub>>2 (mask 4),
//            q0 = sub>>3 (mask 8)
#define NBUCKET 128

__global__ void __launch_bounds__(128, 1)
k2_pqc(int N, int mode, int G,
       const float* __restrict__ theta,
       const float* __restrict__ uW1, const float* __restrict__ ub1,
       const float* __restrict__ uW2, const float* __restrict__ ub2,
       const int* __restrict__ gn, const int* __restrict__ batch,
       const float* __restrict__ hW1, const float* __restrict__ hb1,
       const float* __restrict__ hW2, const float* __restrict__ hb2,
       float* __restrict__ out)
{
    __shared__ float sU[7][8];
    __shared__ float sM[6];
    __shared__ float4 sP1[128];
    __shared__ float2 sP2[128];
    __shared__ float sb2v[2];
    __shared__ float sSeg[NBUCKET * 2];
    __shared__ float sCnt[NBUCKET];
    __shared__ int s_last;
    int tid = threadIdx.x;

    // ---- PDL-overlapped prologue: reads only kernel inputs ----
    if (tid < 9) {
        int g = tid;
        float sx, cx, sy, cy, sz, cz;
        __sincosf(0.5f * theta[3 * g + 0], &sx, &cx);
        __sincosf(0.5f * theta[3 * g + 1], &sy, &cy);
        __sincosf(0.5f * theta[3 * g + 2], &sz, &cz);
        float M00r =  cy*cx, M00i =  sy*sx;
        float M01r = -sy*cx, M01i = -cy*sx;
        float M10r =  sy*cx, M10i = -cy*sx;
        float M11r =  cy*cx, M11i = -sy*sx;
        float u[8];
        u[0] = cz*M00r + sz*M00i;  u[1] = cz*M00i - sz*M00r;
        u[2] = cz*M01r + sz*M01i;  u[3] = cz*M01i - sz*M01r;
        u[4] = cz*M10r - sz*M10i;  u[5] = cz*M10i + sz*M10r;
        u[6] = cz*M11r - sz*M11i;  u[7] = cz*M11i + sz*M11r;
        if (g < 7) {
#pragma unroll
            for (int k = 0; k < 8; k++) sU[g][k] = u[k];
        } else {
            int off = (g == 7) ? 0 : 3;
            sM[off + 0] = u[0]*u[0] + u[1]*u[1] - (u[4]*u[4] + u[5]*u[5]);
            sM[off + 1] = u[0]*u[2] + u[1]*u[3] - (u[4]*u[6] + u[5]*u[7]);
            sM[off + 2] = u[0]*u[3] - u[1]*u[2] - (u[4]*u[7] - u[5]*u[6]);
        }
    }
    {
        int j = tid;   // blockDim == 128 == NBUCKET
        sP1[j] = make_float4(__ldg(uW1 + j), __ldg(uW1 + 128 + j),
                             __ldg(uW1 + 256 + j), __ldg(ub1 + j));
        sP2[j] = make_float2(__ldg(uW2 + 2*j + 0), __ldg(uW2 + 2*j + 1));
        sSeg[2*j + 0] = 0.f; sSeg[2*j + 1] = 0.f;
        sCnt[j] = 0.f;
    }
    if (tid < 2) sb2v[tid] = ub2[tid];

    // ---- wait for k1's results (no-op when launched without PDL) ----
#if __CUDA_ARCH__ >= 900
    cudaGridDependencySynchronize();
#endif
    __syncthreads();

    int sub = tid & 15;
    int t4 = sub & 1, t7 = (sub >> 1) & 1, t8 = (sub >> 2) & 1, t0 = (sub >> 3) & 1;
    int grp = tid >> 4;                        // 0..7
    int rb = blockIdx.x * 16 + grp * 2;        // two consecutive rows per group

    int rowv[2]; rowv[0] = rb; rowv[1] = rb + 1;
    int iv[2]; bool vv[2];
    int i0v[2], i1v[2], i0cv[2];
    float nf0uv[2], nf1uv[2], eAv[2], eBv[2], nA0v[2], nA1v[2], nB0v[2], nB1v[2];

#pragma unroll
    for (int r = 0; r < 2; r++) {
        int i = min(rowv[r], N - 1);
        iv[r] = i; vv[r] = rowv[r] < N;
        int i0 = __ldg(gn + i * 4 + 0), i1 = __ldg(gn + i * 4 + 1);
        int i0c = max(i0, 0), i1c = max(i1, 0);
        i0v[r] = i0; i1v[r] = i1; i0cv[r] = i0c;
        float a = g_node_f[i0c * 2 + 0];
        float b = g_node_f[i0c * 2 + 1];
        float c = g_node_f[i1c * 2 + 0];
        float d = g_node_f[i1c * 2 + 1];
        nf0uv[r] = a; nf1uv[r] = b;
        nA0v[r] = (i0 >= 0) ? a : 0.f;
        nA1v[r] = (i0 >= 0) ? b : 0.f;
        nB0v[r] = (i1 >= 0) ? c : 0.f;
        nB1v[r] = (i1 >= 0) ? d : 0.f;
        eAv[r] = g_eAB[i * 2 + 0];
        eBv[r] = g_eAB[i * 2 + 1];
    }

    float cAv[2], sAv[2], cBv[2], sBv[2];
    float c3av[2], s3av[2], c3bv[2], s3bv[2], c4av[2], s4av[2], c4bv[2], s4bv[2];
#pragma unroll
    for (int r = 0; r < 2; r++) {
        __sincosf(0.5f * eAv[r],  &sAv[r],  &cAv[r]);
        __sincosf(0.5f * eBv[r],  &sBv[r],  &cBv[r]);
        __sincosf(0.5f * nA0v[r], &s3av[r], &c3av[r]);
        __sincosf(0.5f * nA1v[r], &s3bv[r], &c3bv[r]);
        __sincosf(0.5f * nB0v[r], &s4av[r], &c4av[r]);
        __sincosf(0.5f * nB1v[r], &s4bv[r], &c4bv[r]);
    }

    float xr[2], xi[2];
    float mk = ((sub & 6) == 0) ? 1.f : 0.f;
#pragma unroll
    for (int r = 0; r < 2; r++) {
        float f0r = t0 ? sAv[r]*cBv[r]   : cAv[r]*cBv[r];
        float f0i = t0 ? sAv[r]*sBv[r]   : -cAv[r]*sBv[r];
        float f4r = t4 ? s4av[r]*c4bv[r] : c4av[r]*c4bv[r];
        float f4i = t4 ? s4av[r]*s4bv[r] : -c4av[r]*s4bv[r];
        xr[r] = mk*(f0r*f4r - f0i*f4i);
        xi[r] = mk*(f0r*f4i + f0i*f4r);
    }

    // CRX(nB0): control q4 (t4), target q7 (mask 2)
#pragma unroll
    for (int r = 0; r < 2; r++) {
        float pr = SHX(xr[r], 2), pi = SHX(xi[r], 2);
        if (t4) { float nr = c4av[r]*xr[r] + s4av[r]*pi, ni = c4av[r]*xi[r] - s4av[r]*pr;
                  xr[r] = nr; xi[r] = ni; }
    }
    // CRY(eA): control q0 (t0), target q7 (mask 2)
#pragma unroll
    for (int r = 0; r < 2; r++) {
        float pr = SHX(xr[r], 2), pi = SHX(xi[r], 2);
        float ss = t7 ? sAv[r] : -sAv[r];
        if (t0) { xr[r] = cAv[r]*xr[r] + ss*pr; xi[r] = cAv[r]*xi[r] + ss*pi; }
    }
    // CRZ(nB1): control q4 (t4), target q8 (t8) — diagonal
#pragma unroll
    for (int r = 0; r < 2; r++) {
        if (t4) {
            float zs = t8 ? s4bv[r] : -s4bv[r];
            float nr = c4bv[r]*xr[r] - zs*xi[r], ni = c4bv[r]*xi[r] + zs*xr[r];
            xr[r] = nr; xi[r] = ni;
        }
    }
    // CRY(eB): control q0 (t0), target q8 (mask 4)
#pragma unroll
    for (int r = 0; r < 2; r++) {
        float pr = SHX(xr[r], 4), pi = SHX(xi[r], 4);
        float ss = t8 ? sBv[r] : -sBv[r];
        if (t0) { xr[r] = cBv[r]*xr[r] + ss*pr; xi[r] = cBv[r]*xi[r] + ss*pi; }
    }

    float U0,U1,U2,U3,U4,U5,U6,U7;
#define LOADUg(g) { U0=sU[g][0]; U1=sU[g][1]; U2=sU[g][2]; U3=sU[g][3]; \
                    U4=sU[g][4]; U5=sU[g][5]; U6=sU[g][6]; U7=sU[g][7]; }
#define UCROSS2(M, tb) { \
    float Cmr=(tb)?U6:U0, Cmi=(tb)?U7:U1, Cpr=(tb)?U4:U2, Cpi=(tb)?U5:U3; \
    _Pragma("unroll") \
    for (int r = 0; r < 2; r++) { \
        float pr=SHX(xr[r],M), pi=SHX(xi[r],M); \
        float nr = Cmr*xr[r] - Cmi*xi[r] + Cpr*pr - Cpi*pi; \
        float ni = Cmr*xi[r] + Cmi*xr[r] + Cpr*pi + Cpi*pr; \
        xr[r]=nr; xi[r]=ni; } }

    // Block 0: U0 on q0 (mask 8), U1 on q4 (mask 1), U2 on q7 (mask 2)
    LOADUg(0) UCROSS2(8, t0)
    LOADUg(1) UCROSS2(1, t4)
    LOADUg(2) UCROSS2(2, t7)
    if ((t0 & t4) ^ (t4 & t7) ^ (t7 & t0)) {
#pragma unroll
        for (int r = 0; r < 2; r++) { xr[r] = -xr[r]; xi[r] = -xi[r]; }
    }

    // Block 1: U3 on q7 (mask 2), U4 on q4 (mask 1), U5 on q8 (mask 4)
    LOADUg(3) UCROSS2(2, t7)
    LOADUg(4) UCROSS2(1, t4)
    LOADUg(5) UCROSS2(4, t8)
    if ((t7 & t4) ^ (t4 & t8) ^ (t8 & t7)) {
#pragma unroll
        for (int r = 0; r < 2; r++) { xr[r] = -xr[r]; xi[r] = -xi[r]; }
    }

    // S = <chi| M7(q7, mask 2) (x) M8(q8, mask 4) |chi>
    float d7 = sM[0], k7r = sM[1], k7i = sM[2];
    float d8 = sM[3], k8r = sM[4], k8i = sM[5];
    float d8s = t8 ? -d8 : d8, k8is = t8 ? -k8i : k8i;
    float d7s = t7 ? -d7 : d7, k7is = t7 ? -k7i : k7i;
    float Sv[2];
#pragma unroll
    for (int r = 0; r < 2; r++) {
        float pr = SHX(xr[r], 4), pi = SHX(xi[r], 4);
        float ur = d8s*xr[r] + k8r*pr - k8is*pi;
        float ui = d8s*xi[r] + k8r*pi + k8is*pr;
        float qr = SHX(ur, 2), qi = SHX(ui, 2);
        float wr = d7s*ur + k7r*qr - k7is*qi;
        float wi = d7s*ui + k7r*qi + k7is*qr;
        Sv[r] = xr[r]*wr + xi[r]*wi;
    }
#pragma unroll
    for (int r = 0; r < 2; r++) {
        Sv[r] += SHX(Sv[r], 1);
        Sv[r] += SHX(Sv[r], 2);
        Sv[r] += SHX(Sv[r], 4);
        Sv[r] += SHX(Sv[r], 8);
    }

    // q3 scalar per row
    LOADUg(6)
    float exv[2];
#pragma unroll
    for (int r = 0; r < 2; r++) {
        float p0r = c3av[r]*c3bv[r], p0i = -c3av[r]*s3bv[r];
        float p1r = s3av[r]*c3bv[r], p1i = s3av[r]*s3bv[r];
        float a0r = U0*p0r - U1*p0i + U2*p1r - U3*p1i;
        float a0i = U0*p0i + U1*p0r + U2*p1i + U3*p1r;
        float a1r = U4*p0r - U5*p0i + U6*p1r - U7*p1i;
        float a1i = U4*p0i + U5*p0r + U6*p1i + U7*p1r;
        exv[r] = Sv[r] * 2.f * (a0r*a1r + a0i*a1i);
    }
#undef LOADUg
#undef UCROSS2

    // upd MLP: 3 -> 128 (leaky) -> 2, hidden split j = 16u + sub, both rows
    float acc0[2] = {0.f, 0.f}, acc1[2] = {0.f, 0.f};
#pragma unroll
    for (int u = 0; u < 8; u++) {
        int j = 16*u + sub;
        float4 wv = sP1[j];
        float2 v = sP2[j];
#pragma unroll
        for (int r = 0; r < 2; r++) {
            float h = fmaf(nf0uv[r], wv.x, fmaf(nf1uv[r], wv.y, fmaf(exv[r], wv.z, wv.w)));
            h = leaky(h);
            acc0[r] = fmaf(h, v.x, acc0[r]);
            acc1[r] = fmaf(h, v.y, acc1[r]);
        }
    }
#pragma unroll
    for (int r = 0; r < 2; r++) {
        acc0[r] += SHX(acc0[r], 1); acc0[r] += SHX(acc0[r], 2);
        acc0[r] += SHX(acc0[r], 4); acc0[r] += SHX(acc0[r], 8);
        acc1[r] += SHX(acc1[r], 1); acc1[r] += SHX(acc1[r], 2);
        acc1[r] += SHX(acc1[r], 4); acc1[r] += SHX(acc1[r], 8);
    }

    if (sub == 0) {
#pragma unroll
        for (int r = 0; r < 2; r++) {
            if (!vv[r]) continue;
            float a0 = acc0[r] + sb2v[0];
            float a1 = acc1[r] + sb2v[1];
            int i = iv[r];
            if (mode == 1) {
                int gi = batch[i];
                float nfa = g_node_f[i * 2 + 0];
                float nfb = g_node_f[i * 2 + 1];
                if (gi < NBUCKET) {
                    atomicAdd(&sSeg[gi * 2 + 0], nfa);
                    atomicAdd(&sSeg[gi * 2 + 1], nfb);
                    atomicAdd(&sCnt[gi], 1.f);
                } else {
                    atomicAdd(&g_seg[gi * 2 + 0], nfa);
                    atomicAdd(&g_seg[gi * 2 + 1], nfb);
                    atomicAdd(&g_cnt[gi], 1.f);
                }
                int gt = batch[i0cv[r]];
                if (gt < NBUCKET) {
                    atomicAdd(&sSeg[gt * 2 + 0], a0);
                    atomicAdd(&sSeg[gt * 2 + 1], a1);
                } else {
                    atomicAdd(&g_seg[gt * 2 + 0], a0);
                    atomicAdd(&g_seg[gt * 2 + 1], a1);
                }
            } else {
                g_upd[i * 2 + 0] = a0;
                g_upd[i * 2 + 1] = a1;
            }
        }
    }

    if (mode == 1) {
        __syncthreads();
        {
            int j = tid;
            float c = sCnt[j];
            float s0 = sSeg[2*j + 0], s1 = sSeg[2*j + 1];
            if (c != 0.f) atomicAdd(&g_cnt[j], c);
            if (s0 != 0.f) atomicAdd(&g_seg[2*j + 0], s0);
            if (s1 != 0.f) atomicAdd(&g_seg[2*j + 1], s1);
        }

        __threadfence();
        __syncthreads();
        if (tid == 0) s_last = (atomicAdd(&g_ctr, 1) == (int)gridDim.x - 1) ? 1 : 0;
        __syncthreads();
        if (s_last) {
            for (int g = tid; g < G; g += 128) {
                float c = ldcg(&g_cnt[g]);
                float inv = (c > 0.f) ? (1.f / c) : 0.f;
                float e0 = ldcg(&g_seg[g * 2 + 0]) * inv;
                float e1 = ldcg(&g_seg[g * 2 + 1]) * inv;
                float h0 = leaky(e0 * hW1[0] + e1 * hW1[2] + hb1[0]);
                float h1 = leaky(e0 * hW1[1] + e1 * hW1[3] + hb1[1]);
                out[g * 2 + 0] = h0 * hW2[0] + h1 * hW2[2] + hb2[0];
                out[g * 2 + 1] = h0 * hW2[1] + h1 * hW2[3] + hb2[1];
            }
        }
    }
}

// =================== legacy multi-hop path (H > 1 only) ======================
__global__ void k1_feat_legacy(const float* __restrict__ node_feat, int N,
                               const float* __restrict__ edge_attr,
                               const float* __restrict__ nW1, const float* __restrict__ nb1,
                               const float* __restrict__ nW2, const float* __restrict__ nb2,
                               const float* __restrict__ eW1, const float* __restrict__ eb1,
                               const float* __restrict__ eW2, const float* __restrict__ eb2,
                               const int* __restrict__ ge)
{
    int i = blockIdx.x * blockDim.x + threadIdx.x;
    if (i < GMAX * 2) g_seg[i] = 0.f;
    else if (i < GMAX * 3) g_cnt[i - GMAX * 2] = 0.f;
    if (i == 0) g_ctr = 0;
    if (i >= N) return;

    float x[16];
    for (int k = 0; k < 16; k++) x[k] = node_feat[i * 16 + k];
    float o0 = nb2[0], o1 = nb2[1];
    for (int j = 0; j < 128; j++) {
        float h = nb1[j];
        for (int k = 0; k < 16; k++) h = fmaf(x[k], nW1[k * 128 + j], h);
        h = leaky(h);
        o0 = fmaf(h, nW2[j * 2 + 0], o0);
        o1 = fmaf(h, nW2[j * 2 + 1], o1);
    }
    g_node_f[i * 2 + 0] = tanhf(o0) * PI_F;
    g_node_f[i * 2 + 1] = tanhf(o1) * PI_F;

    int eidx = ge[i * 3];
    float eAv = 0.f, eBv = 0.f;
    if (eidx >= 0) {
        float y[8];
        for (int k = 0; k < 8; k++) y[k] = edge_attr[eidx * 8 + k];
        float p0 = eb2[0], p1 = eb2[1];
        for (int j = 0; j < 128; j++) {
            float h = eb1[j];
            for (int k = 0; k < 8; k++) h = fmaf(y[k], eW1[k * 128 + j], h);
            h = leaky(h);
            p0 = fmaf(h, eW2[j * 2 + 0], p0);
            p1 = fmaf(h, eW2[j * 2 + 1], p1);
        }
        eAv = tanhf(p0) * PI_F;
        eBv = tanhf(p1) * PI_F;
    }
    g_eAB[i * 2 + 0] = eAv;
    g_eAB[i * 2 + 1] = eBv;
}

__global__ void k2_legacy(int N, const float* __restrict__ theta,
                          const float* __restrict__ uW1, const float* __restrict__ ub1,
                          const float* __restrict__ uW2, const float* __restrict__ ub2,
                          const int* __restrict__ gn)
{
    int i = blockIdx.x * blockDim.x + threadIdx.x;
    if (i >= N) return;

    int i0 = gn[i * 4 + 0], i1 = gn[i * 4 + 1];
    int i0c = max(i0, 0), i1c = max(i1, 0);
    float nf0u = g_node_f[i0c * 2 + 0];
    float nf1u = g_node_f[i0c * 2 + 1];
    float nA0 = (i0 >= 0) ? nf0u : 0.f;
    float nA1 = (i0 >= 0) ? nf1u : 0.f;
    float nB0 = (i1 >= 0) ? g_node_f[i1c * 2 + 0] : 0.f;
    float nB1 = (i1 >= 0) ? g_node_f[i1c * 2 + 1] : 0.f;
    float eA = g_eAB[i * 2 + 0], eB = g_eAB[i * 2 + 1];

    float re[32], im[32];
    for (int m = 0; m < 32; m++) { re[m] = 0.f; im[m] = 0.f; }
    re[0] = 1.f;
    float angsA[3] = {eA, nA0, nB0};
    float angsB[3] = {eB, nA1, nB1};
    int bits[3] = {1, 2, 4};
    for (int q = 0; q < 3; q++) {
        float c, s; sincosf(0.5f * angsA[q], &s, &c);
        int B = bits[q];
        for (int m = 0; m < 32; m++) if (!(m & B)) {
            int h = m | B;
            float r0 = re[m], i0v = im[m], r1 = re[h], i1v = im[h];
            re[m] = c*r0 - s*r1; im[m] = c*i0v - s*i1v;
            re[h] = s*r0 + c*r1; im[h] = s*i0v + c*i1v;
        }
        sincosf(0.5f * angsB[q], &s, &c);
        for (int m = 0; m < 32; m++) {
            float r = re[m], ii = im[m];
            if (m & B) { re[m] = c*r - s*ii; im[m] = c*ii + s*r; }
            else       { re[m] = c*r + s*ii; im[m] = c*ii - s*r; }
        }
    }
    {
        float c, s; sincosf(0.5f * nB0, &s, &c);
        for (int m = 0; m < 32; m++) if ((m & 4) && !(m & 8)) {
            int h = m | 8;
            float r0 = re[m], i0v = im[m], r1 = re[h], i1v = im[h];
            re[m] = c*r0 + s*i1v; im[m] = c*i0v - s*r1;
            re[h] = c*r1 + s*i0v; im[h] = c*i1v - s*r0;
        }
        sincosf(0.5f * eA, &s, &c);
        for (int m = 0; m < 32; m++) if ((m & 1) && !(m & 8)) {
            int h = m | 8;
            float r0 = re[m], i0v = im[m], r1 = re[h], i1v = im[h];
            re[m] = c*r0 - s*r1; im[m] = c*i0v - s*i1v;
            re[h] = s*r0 + c*r1; im[h] = s*i0v + c*i1v;
        }
        sincosf(0.5f * nB1, &s, &c);
        for (int m = 0; m < 32; m++) if (m & 4) {
            float r = re[m], ii = im[m];
            if (m & 16) { re[m] = c*r - s*ii; im[m] = c*ii + s*r; }
            else        { re[m] = c*r + s*ii; im[m] = c*ii - s*r; }
        }
        sincosf(0.5f * eB, &s, &c);
        for (int m = 0; m < 32; m++) if ((m & 1) && !(m & 16)) {
            int h = m | 16;
            float r0 = re[m], i0v = im[m], r1 = re[h], i1v = im[h];
            re[m] = c*r0 - s*r1; im[m] = c*i0v - s*i1v;
            re[h] = s*r0 + c*r1; im[h] = s*i0v + c*i1v;
        }
    }
    int qb[3][3] = {{1, 4, 8}, {8, 4, 16}, {2, 8, 16}};
    for (int b = 0; b < 3; b++) {
        for (int qq = 0; qq < 3; qq++) {
            int B = qb[b][qq];
            for (int gset = 0; gset < 3; gset++) {
                float c, s; sincosf(0.5f * theta[9*b + 3*qq + gset], &s, &c);
                if (gset == 0) {
                    for (int m = 0; m < 32; m++) if (!(m & B)) {
                        int h = m | B;
                        float r0 = re[m], i0v = im[m], r1 = re[h], i1v = im[h];
                        re[m] = c*r0 + s*i1v; im[m] = c*i0v - s*r1;
                        re[h] = c*r1 + s*i0v; im[h] = c*i1v - s*r0;
                    }
                } else if (gset == 1) {
                    for (int m = 0; m < 32; m++) if (!(m & B)) {
                        int h = m | B;
                        float r0 = re[m], i0v = im[m], r1 = re[h], i1v = im[h];
                        re[m] = c*r0 - s*r1; im[m] = c*i0v - s*i1v;
                        re[h] = s*r0 + c*r1; im[h] = s*i0v + c*i1v;
                    }
                } else {
                    for (int m = 0; m < 32; m++) {
                        float r = re[m], ii = im[m];
                        if (m & B) { re[m] = c*r - s*ii; im[m] = c*ii + s*r; }
                        else       { re[m] = c*r + s*ii; im[m] = c*ii - s*r; }
                    }
                }
            }
        }
        for (int e = 0; e < 3; e++) {
            int B1 = qb[b][e], B2 = qb[b][(e + 1) % 3];
            for (int m = 0; m < 32; m++) if ((m & B1) && (m & B2)) { re[m] = -re[m]; im[m] = -im[m]; }
        }
    }
    float ex = 0.f;
    for (int m = 0; m < 32; m++) ex += re[m]*re[m ^ 2] + im[m]*im[m ^ 2];

    float u0 = ub2[0], u1 = ub2[1];
    for (int j = 0; j < 128; j++) {
        float h = ub1[j];
        h = fmaf(nf0u, uW1[j], h);
        h = fmaf(nf1u, uW1[128 + j], h);
        h = fmaf(ex,   uW1[256 + j], h);
        h = leaky(h);
        u0 = fmaf(h, uW2[j * 2 + 0], u0);
        u1 = fmaf(h, uW2[j * 2 + 1], u1);
    }
    g_upd[i * 2 + 0] = u0;
    g_upd[i * 2 + 1] = u1;
}

__global__ void k2_scatter(int N, const int* __restrict__ gn)
{
    int i = blockIdx.x * blockDim.x + threadIdx.x;
    if (i >= N) return;
    int t = max(gn[i * 4], 0);
    atomicAdd(&g_node_f[t * 2 + 0], g_upd[i * 2 + 0]);
    atomicAdd(&g_node_f[t * 2 + 1], g_upd[i * 2 + 1]);
}

__global__ void k_seg(int N, const int* __restrict__ batch)
{
    int i = blockIdx.x * blockDim.x + threadIdx.x;
    if (i >= N) return;
    int g = batch[i];
    atomicAdd(&g_seg[g * 2 + 0], g_node_f[i * 2 + 0]);
    atomicAdd(&g_seg[g * 2 + 1], g_node_f[i * 2 + 1]);
    atomicAdd(&g_cnt[g], 1.f);
}

__global__ void k3_head(int G,
                        const float* __restrict__ hW1, const float* __restrict__ hb1,
                        const float* __restrict__ hW2, const float* __restrict__ hb2,
                        float* __restrict__ out)
{
    int g = blockIdx.x * blockDim.x + threadIdx.x;
    if (g >= G) return;
    float c = g_cnt[g];
    float inv = (c > 0.f) ? (1.f / c) : 0.f;
    float e0 = g_seg[g * 2 + 0] * inv;
    float e1 = g_seg[g * 2 + 1] * inv;
    float h0 = leaky(e0 * hW1[0] + e1 * hW1[2] + hb1[0]);
    float h1 = leaky(e0 * hW1[1] + e1 * hW1[3] + hb1[1]);
    out[g * 2 + 0] = h0 * hW2[0] + h1 * hW2[2] + hb2[0];
    out[g * 2 + 1] = h0 * hW2[1] + h1 * hW2[3] + hb2[1];
}

extern "C" void kernel_launch(void* const* d_in, const int* in_sizes, int n_in,
                              void* d_out, int out_size)
{
    const float* node_feat = (const float*)d_in[0];
    const float* edge_attr = (const float*)d_in[1];
    const float* nW1 = (const float*)d_in[2];
    const float* nb1 = (const float*)d_in[3];
    const float* nW2 = (const float*)d_in[4];
    const float* nb2 = (const float*)d_in[5];
    const float* eW1 = (const float*)d_in[6];
    const float* eb1 = (const float*)d_in[7];
    const float* eW2 = (const float*)d_in[8];
    const float* eb2 = (const float*)d_in[9];
    const float* theta = (const float*)d_in[10];
    const float* uW1 = (const float*)d_in[11];
    const float* ub1 = (const float*)d_in[12];
    const float* uW2 = (const float*)d_in[13];
    const float* ub2 = (const float*)d_in[14];
    const float* hW1 = (const float*)d_in[15];
    const float* hb1 = (const float*)d_in[16];
    const float* hW2 = (const float*)d_in[17];
    const float* hb2 = (const float*)d_in[18];
    const int* gn = (const int*)d_in[19];
    const int* ge = (const int*)d_in[20];
    const int* batch = (const int*)d_in[21];

    int N = in_sizes[0] / 16;
    int H = in_sizes[10] / 27;
    int G = out_size / 2;

    if (H == 1) {
        // k1: 4 rows/warp (R14-optimal), 16 rows/block
        int k1blocks = (N + 15) / 16;
        k1_feat<<<k1blocks, 128>>>(node_feat, N, edge_attr, nW1, nb1, nW2, nb2,
                                   eW1, eb1, eW2, eb2, ge);

        // k2 with PDL: 16 rows/block (2 rows per 16-thread group)
        int k2blocks = (N + 15) / 16;
        cudaLaunchConfig_t cfg = {};
        cfg.gridDim = dim3(k2blocks, 1, 1);
        cfg.blockDim = dim3(128, 1, 1);
        cfg.dynamicSmemBytes = 0;
        cfg.stream = 0;
        cudaLaunchAttribute attrs[1];
        attrs[0].id = cudaLaunchAttributeProgrammaticStreamSerialization;
        attrs[0].val.programmaticStreamSerializationAllowed = 1;
        cfg.attrs = attrs;
        cfg.numAttrs = 1;
        cudaError_t err = cudaLaunchKernelEx(&cfg, k2_pqc,
                                             N, 1, G, theta, uW1, ub1, uW2, ub2,
                                             gn, batch, hW1, hb1, hW2, hb2,
                                             (float*)d_out);
        if (err != cudaSuccess) {
            k2_pqc<<<k2blocks, 128>>>(N, 1, G, theta, uW1, ub1, uW2, ub2,
                                      gn, batch, hW1, hb1, hW2, hb2,
                                      (float*)d_out);
        }
    } else {
        const int T = 128;
        int nbs = (N + T - 1) / T;
        k1_feat_legacy<<<nbs, T>>>(node_feat, N, edge_attr, nW1, nb1, nW2, nb2,
                                   eW1, eb1, eW2, eb2, ge);
        for (int h = 0; h < H; h++) {
            k2_legacy<<<nbs, T>>>(N, theta + 27 * h,
                                  uW1 + 384 * h, ub1 + 128 * h,
                                  uW2 + 256 * h, ub2 + 2 * h, gn);
            k2_scatter<<<nbs, T>>>(N, gn);
        }
        k_seg<<<nbs, T>>>(N, batch);
        k3_head<<<(G + 127) / 128, 128>>>(G, hW1, hb1, hW2, hb2, (float*)d_out);
    }
}

// round 17
// speedup vs baseline: 1.6834x; 1.6834x over previous
#include <cuda_runtime.h>
#include <math.h>
#include <stdint.h>

#define NMAX 16384
#define GMAX 1024
#define PI_F 3.14159265358979323846f

__device__ float g_node_f[NMAX * 2];
__device__ float g_eAB[NMAX * 2];
__device__ float g_upd[NMAX * 2];
__device__ float g_seg[GMAX * 2];
__device__ float g_cnt[GMAX];
__device__ int   g_ctr;

__device__ __forceinline__ float leaky(float x) { return x > 0.f ? x : 0.2f * x; }

__device__ __forceinline__ float ldcg(const float* p) {
    float v; asm volatile("ld.global.cg.f32 %0, [%1];" : "=f"(v) : "l"(p)); return v;
}

#define SHX(v, m) __shfl_xor_sync(0xffffffffu, (v), (m))

// ---------------- K1: 4 rows per warp, weights register-resident (R14 exact) -
__global__ void __launch_bounds__(128, 1)
k1_feat(const float* __restrict__ node_feat, int N,
        const float* __restrict__ edge_attr,
        const float* __restrict__ nW1, const float* __restrict__ nb1,
        const float* __restrict__ nW2, const float* __restrict__ nb2,
        const float* __restrict__ eW1, const float* __restrict__ eb1,
        const float* __restrict__ eW2, const float* __restrict__ eb2,
        const int* __restrict__ ge)
{
    int tid = threadIdx.x;
    int lane = tid & 31;
    int w = tid >> 5;
    int gtid = blockIdx.x * blockDim.x + tid;

    if (gtid < GMAX * 2) g_seg[gtid] = 0.f;
    else if (gtid < GMAX * 3) g_cnt[gtid - GMAX * 2] = 0.f;
    if (gtid == 0) g_ctr = 0;

    int j0 = 4 * lane;

    float wn[16][4];
#pragma unroll
    for (int k = 0; k < 16; k++) {
#pragma unroll
        for (int q = 0; q < 4; q++) wn[k][q] = __ldg(nW1 + k * 128 + j0 + q);
    }
    float bn[4], n2[4][2];
#pragma unroll
    for (int q = 0; q < 4; q++) {
        bn[q] = __ldg(nb1 + j0 + q);
        n2[q][0] = __ldg(nW2 + 2 * (j0 + q) + 0);
        n2[q][1] = __ldg(nW2 + 2 * (j0 + q) + 1);
    }
    float we[8][4];
#pragma unroll
    for (int k = 0; k < 8; k++) {
#pragma unroll
        for (int q = 0; q < 4; q++) we[k][q] = __ldg(eW1 + k * 128 + j0 + q);
    }
    float be[4], e2[4][2];
#pragma unroll
    for (int q = 0; q < 4; q++) {
        be[q] = __ldg(eb1 + j0 + q);
        e2[q][0] = __ldg(eW2 + 2 * (j0 + q) + 0);
        e2[q][1] = __ldg(eW2 + 2 * (j0 + q) + 1);
    }
    float nb2x = __ldg(nb2 + 0), nb2y = __ldg(nb2 + 1);
    float eb2x = __ldg(eb2 + 0), eb2y = __ldg(eb2 + 1);

    int warpId = blockIdx.x * (blockDim.x >> 5) + w;
    int base = warpId * 4;

#pragma unroll
    for (int rr = 0; rr < 4; rr++) {
        int row = base + rr;
        bool valid = row < N;
        int ic = min(row, N - 1);

        float x[16];
#pragma unroll
        for (int k = 0; k < 16; k++) x[k] = __ldg(node_feat + ic * 16 + k);

        float h[4] = {bn[0], bn[1], bn[2], bn[3]};
#pragma unroll
        for (int k = 0; k < 16; k++) {
#pragma unroll
            for (int q = 0; q < 4; q++) h[q] = fmaf(x[k], wn[k][q], h[q]);
        }
        float o0 = 0.f, o1 = 0.f;
#pragma unroll
        for (int q = 0; q < 4; q++) {
            float hq = leaky(h[q]);
            o0 = fmaf(hq, n2[q][0], o0);
            o1 = fmaf(hq, n2[q][1], o1);
        }

        int eidx = __ldg(ge + ic * 3);
        int ec = max(eidx, 0);
        float y[8];
#pragma unroll
        for (int k = 0; k < 8; k++) y[k] = __ldg(edge_attr + ec * 8 + k);

        float g[4] = {be[0], be[1], be[2], be[3]};
#pragma unroll
        for (int k = 0; k < 8; k++) {
#pragma unroll
            for (int q = 0; q < 4; q++) g[q] = fmaf(y[k], we[k][q], g[q]);
        }
        float p0 = 0.f, p1 = 0.f;
#pragma unroll
        for (int q = 0; q < 4; q++) {
            float gq = leaky(g[q]);
            p0 = fmaf(gq, e2[q][0], p0);
            p1 = fmaf(gq, e2[q][1], p1);
        }

#pragma unroll
        for (int off = 16; off >= 1; off >>= 1) {
            o0 += SHX(o0, off);
            o1 += SHX(o1, off);
            p0 += SHX(p0, off);
            p1 += SHX(p1, off);
        }

        if (lane == 0 && valid) {
            g_node_f[row * 2 + 0] = tanhf(o0 + nb2x) * PI_F;
            g_node_f[row * 2 + 1] = tanhf(o1 + nb2y) * PI_F;
            g_eAB[row * 2 + 0] = (eidx >= 0) ? tanhf(p0 + eb2x) * PI_F : 0.f;
            g_eAB[row * 2 + 1] = (eidx >= 0) ? tanhf(p1 + eb2y) * PI_F : 0.f;
        }
    }
}

// ---------------- K2: 16 threads/row; PDL + hoisted gn gathers --------------
// lane bits: q4 = sub&1 (mask 1), q7 = sub>>1 (mask 2), q8 = sub>>2 (mask 4),
//            q0 = sub>>3 (mask 8)
#define NBUCKET 128

__global__ void __launch_bounds__(128, 1)
k2_pqc(int N, int mode, int G,
       const float* __restrict__ theta,
       const float* __restrict__ uW1, const float* __restrict__ ub1,
       const float* __restrict__ uW2, const float* __restrict__ ub2,
       const int* __restrict__ gn, const int* __restrict__ batch,
       const float* __restrict__ hW1, const float* __restrict__ hb1,
       const float* __restrict__ hW2, const float* __restrict__ hb2,
       float* __restrict__ out)
{
    __shared__ float sU[7][8];
    __shared__ float sM[6];
    __shared__ float4 sP1[128];
    __shared__ float2 sP2[128];
    __shared__ float sb2v[2];
    __shared__ float sSeg[NBUCKET * 2];
    __shared__ float sCnt[NBUCKET];
    __shared__ int s_last;
    int tid = threadIdx.x;

    // ---- hoisted index gathers: gn/batch are kernel INPUTS (not k1 outputs) -
    int sub = tid & 15;
    int t4 = sub & 1, t7 = (sub >> 1) & 1, t8 = (sub >> 2) & 1, t0 = (sub >> 3) & 1;
    int row = (blockIdx.x * 128 + tid) >> 4;
    int i = min(row, N - 1);
    bool valid = row < N;
    int i0 = __ldg(gn + i * 4 + 0), i1 = __ldg(gn + i * 4 + 1);
    int i0c = max(i0, 0), i1c = max(i1, 0);

    // ---- PDL-overlapped prologue: reads only kernel inputs ----
    if (tid < 9) {
        int g = tid;
        float sx, cx, sy, cy, sz, cz;
        __sincosf(0.5f * theta[3 * g + 0], &sx, &cx);
        __sincosf(0.5f * theta[3 * g + 1], &sy, &cy);
        __sincosf(0.5f * theta[3 * g + 2], &sz, &cz);
        float M00r =  cy*cx, M00i =  sy*sx;
        float M01r = -sy*cx, M01i = -cy*sx;
        float M10r =  sy*cx, M10i = -cy*sx;
        float M11r =  cy*cx, M11i = -sy*sx;
        float u[8];
        u[0] = cz*M00r + sz*M00i;  u[1] = cz*M00i - sz*M00r;
        u[2] = cz*M01r + sz*M01i;  u[3] = cz*M01i - sz*M01r;
        u[4] = cz*M10r - sz*M10i;  u[5] = cz*M10i + sz*M10r;
        u[6] = cz*M11r - sz*M11i;  u[7] = cz*M11i + sz*M11r;
        if (g < 7) {
#pragma unroll
            for (int k = 0; k < 8; k++) sU[g][k] = u[k];
        } else {
            int off = (g == 7) ? 0 : 3;
            sM[off + 0] = u[0]*u[0] + u[1]*u[1] - (u[4]*u[4] + u[5]*u[5]);
            sM[off + 1] = u[0]*u[2] + u[1]*u[3] - (u[4]*u[6] + u[5]*u[7]);
            sM[off + 2] = u[0]*u[3] - u[1]*u[2] - (u[4]*u[7] - u[5]*u[6]);
        }
    }
    {
        int j = tid;   // blockDim == 128 == NBUCKET
        sP1[j] = make_float4(__ldg(uW1 + j), __ldg(uW1 + 128 + j),
                             __ldg(uW1 + 256 + j), __ldg(ub1 + j));
        sP2[j] = make_float2(__ldg(uW2 + 2*j + 0), __ldg(uW2 + 2*j + 1));
        sSeg[2*j + 0] = 0.f; sSeg[2*j + 1] = 0.f;
        sCnt[j] = 0.f;
    }
    if (tid < 2) sb2v[tid] = ub2[tid];

    // ---- wait for k1's results (no-op when launched without PDL) ----
#if __CUDA_ARCH__ >= 900
    cudaGridDependencySynchronize();
#endif
    __syncthreads();

    float nf0u = g_node_f[i0c * 2 + 0];
    float nf1u = g_node_f[i0c * 2 + 1];
    float nB0r = g_node_f[i1c * 2 + 0];
    float nB1r = g_node_f[i1c * 2 + 1];
    float eA = g_eAB[i * 2 + 0], eB = g_eAB[i * 2 + 1];

    float nA0 = (i0 >= 0) ? nf0u : 0.f;
    float nA1 = (i0 >= 0) ? nf1u : 0.f;
    float nB0 = (i1 >= 0) ? nB0r : 0.f;
    float nB1 = (i1 >= 0) ? nB1r : 0.f;

    float cA, sA, cB, sB, c3a, s3a, c3b, s3b, c4a, s4a, c4b, s4b;
    __sincosf(0.5f * eA,  &sA,  &cA);
    __sincosf(0.5f * eB,  &sB,  &cB);
    __sincosf(0.5f * nA0, &s3a, &c3a);
    __sincosf(0.5f * nA1, &s3b, &c3b);
    __sincosf(0.5f * nB0, &s4a, &c4a);
    __sincosf(0.5f * nB1, &s4b, &c4b);

    // init: amp(t0,t4,t7,t8) = f0[t0]*f4[t4] if t7==t8==0
    float f0r = t0 ? sA*cB  : cA*cB;
    float f0i = t0 ? sA*sB  : -cA*sB;
    float f4r = t4 ? s4a*c4b : c4a*c4b;
    float f4i = t4 ? s4a*s4b : -c4a*s4b;
    float mk = ((sub & 6) == 0) ? 1.f : 0.f;
    float xr = mk*(f0r*f4r - f0i*f4i);
    float xi = mk*(f0r*f4i + f0i*f4r);

    // CRX(nB0): control q4 (t4), target q7 (mask 2)
    {
        float pr = SHX(xr, 2), pi = SHX(xi, 2);
        if (t4) { float nr = c4a*xr + s4a*pi, ni = c4a*xi - s4a*pr; xr = nr; xi = ni; }
    }
    // CRY(eA): control q0 (t0), target q7 (mask 2)
    {
        float pr = SHX(xr, 2), pi = SHX(xi, 2);
        float ss = t7 ? sA : -sA;
        if (t0) { xr = cA*xr + ss*pr; xi = cA*xi + ss*pi; }
    }
    // CRZ(nB1): control q4 (t4), target q8 (t8) — diagonal
    if (t4) {
        float zs = t8 ? s4b : -s4b;
        float nr = c4b*xr - zs*xi, ni = c4b*xi + zs*xr; xr = nr; xi = ni;
    }
    // CRY(eB): control q0 (t0), target q8 (mask 4)
    {
        float pr = SHX(xr, 4), pi = SHX(xi, 4);
        float ss = t8 ? sB : -sB;
        if (t0) { xr = cB*xr + ss*pr; xi = cB*xi + ss*pi; }
    }

    float U0,U1,U2,U3,U4,U5,U6,U7;
#define LOADUg(g) { U0=sU[g][0]; U1=sU[g][1]; U2=sU[g][2]; U3=sU[g][3]; \
                    U4=sU[g][4]; U5=sU[g][5]; U6=sU[g][6]; U7=sU[g][7]; }
#define UCROSS1(M, tb) { \
    float Cmr=(tb)?U6:U0, Cmi=(tb)?U7:U1, Cpr=(tb)?U4:U2, Cpi=(tb)?U5:U3; \
    float pr=SHX(xr,M), pi=SHX(xi,M); \
    float nr = Cmr*xr - Cmi*xi + Cpr*pr - Cpi*pi; \
    float ni = Cmr*xi + Cmi*xr + Cpr*pi + Cpi*pr; \
    xr=nr; xi=ni; }

    // Block 0: U0 on q0 (mask 8), U1 on q4 (mask 1), U2 on q7 (mask 2)
    LOADUg(0) UCROSS1(8, t0)
    LOADUg(1) UCROSS1(1, t4)
    LOADUg(2) UCROSS1(2, t7)
    if ((t0 & t4) ^ (t4 & t7) ^ (t7 & t0)) { xr = -xr; xi = -xi; }

    // Block 1: U3 on q7 (mask 2), U4 on q4 (mask 1), U5 on q8 (mask 4)
    LOADUg(3) UCROSS1(2, t7)
    LOADUg(4) UCROSS1(1, t4)
    LOADUg(5) UCROSS1(4, t8)
    if ((t7 & t4) ^ (t4 & t8) ^ (t8 & t7)) { xr = -xr; xi = -xi; }

    // S = <chi| M7(q7, mask 2) (x) M8(q8, mask 4) |chi>
    float d7 = sM[0], k7r = sM[1], k7i = sM[2];
    float d8 = sM[3], k8r = sM[4], k8i = sM[5];
    float d8s = t8 ? -d8 : d8, k8is = t8 ? -k8i : k8i;
    float d7s = t7 ? -d7 : d7, k7is = t7 ? -k7i : k7i;
    float S;
    {
        float pr = SHX(xr, 4), pi = SHX(xi, 4);
        float ur = d8s*xr + k8r*pr - k8is*pi;
        float ui = d8s*xi + k8r*pi + k8is*pr;
        float qr = SHX(ur, 2), qi = SHX(ui, 2);
        float wr = d7s*ur + k7r*qr - k7is*qi;
        float wi = d7s*ui + k7r*qi + k7is*qr;
        S = xr*wr + xi*wi;
    }
    S += SHX(S, 1);
    S += SHX(S, 2);
    S += SHX(S, 4);
    S += SHX(S, 8);

    // q3 scalar
    LOADUg(6)
    {
        float p0r = c3a*c3b, p0i = -c3a*s3b, p1r = s3a*c3b, p1i = s3a*s3b;
        float a0r = U0*p0r - U1*p0i + U2*p1r - U3*p1i;
        float a0i = U0*p0i + U1*p0r + U2*p1i + U3*p1r;
        float a1r = U4*p0r - U5*p0i + U6*p1r - U7*p1i;
        float a1i = U4*p0i + U5*p0r + U6*p1i + U7*p1r;
        S *= 2.f * (a0r*a1r + a0i*a1i);
    }
    float ex = S;
#undef LOADUg
#undef UCROSS1

    // upd MLP: 3 -> 128 (leaky) -> 2, hidden split j = 16u + sub
    float acc0 = 0.f, acc1 = 0.f;
#pragma unroll
    for (int u = 0; u < 8; u++) {
        int j = 16*u + sub;
        float4 wv = sP1[j];
        float h = fmaf(nf0u, wv.x, fmaf(nf1u, wv.y, fmaf(ex, wv.z, wv.w)));
        h = leaky(h);
        float2 v = sP2[j];
        acc0 = fmaf(h, v.x, acc0);
        acc1 = fmaf(h, v.y, acc1);
    }
    acc0 += SHX(acc0, 1); acc0 += SHX(acc0, 2); acc0 += SHX(acc0, 4); acc0 += SHX(acc0, 8);
    acc1 += SHX(acc1, 1); acc1 += SHX(acc1, 2); acc1 += SHX(acc1, 4); acc1 += SHX(acc1, 8);

    if (sub == 0 && valid) {
        acc0 += sb2v[0]; acc1 += sb2v[1];
        if (mode == 1) {
            int gi = batch[i];
            float nfa = g_node_f[i * 2 + 0];
            float nfb = g_node_f[i * 2 + 1];
            if (gi < NBUCKET) {
                atomicAdd(&sSeg[gi * 2 + 0], nfa);
                atomicAdd(&sSeg[gi * 2 + 1], nfb);
                atomicAdd(&sCnt[gi], 1.f);
            } else {
                atomicAdd(&g_seg[gi * 2 + 0], nfa);
                atomicAdd(&g_seg[gi * 2 + 1], nfb);
                atomicAdd(&g_cnt[gi], 1.f);
            }
            int gt = batch[i0c];
            if (gt < NBUCKET) {
                atomicAdd(&sSeg[gt * 2 + 0], acc0);
                atomicAdd(&sSeg[gt * 2 + 1], acc1);
            } else {
                atomicAdd(&g_seg[gt * 2 + 0], acc0);
                atomicAdd(&g_seg[gt * 2 + 1], acc1);
            }
        } else {
            g_upd[i * 2 + 0] = acc0;
            g_upd[i * 2 + 1] = acc1;
        }
    }

    if (mode == 1) {
        __syncthreads();
        {
            int j = tid;
            float c = sCnt[j];
            float s0 = sSeg[2*j + 0], s1 = sSeg[2*j + 1];
            if (c != 0.f) atomicAdd(&g_cnt[j], c);
            if (s0 != 0.f) atomicAdd(&g_seg[2*j + 0], s0);
            if (s1 != 0.f) atomicAdd(&g_seg[2*j + 1], s1);
        }

        __threadfence();
        __syncthreads();
        if (tid == 0) s_last = (atomicAdd(&g_ctr, 1) == (int)gridDim.x - 1) ? 1 : 0;
        __syncthreads();
        if (s_last) {
            for (int g = tid; g < G; g += 128) {
                float c = ldcg(&g_cnt[g]);
                float inv = (c > 0.f) ? (1.f / c) : 0.f;
                float e0 = ldcg(&g_seg[g * 2 + 0]) * inv;
                float e1 = ldcg(&g_seg[g * 2 + 1]) * inv;
                float h0 = leaky(e0 * hW1[0] + e1 * hW1[2] + hb1[0]);
                float h1 = leaky(e0 * hW1[1] + e1 * hW1[3] + hb1[1]);
                out[g * 2 + 0] = h0 * hW2[0] + h1 * hW2[2] + hb2[0];
                out[g * 2 + 1] = h0 * hW2[1] + h1 * hW2[3] + hb2[1];
            }
        }
    }
}

// =================== legacy multi-hop path (H > 1 only) ======================
__global__ void k1_feat_legacy(const float* __restrict__ node_feat, int N,
                               const float* __restrict__ edge_attr,
                               const float* __restrict__ nW1, const float* __restrict__ nb1,
                               const float* __restrict__ nW2, const float* __restrict__ nb2,
                               const float* __restrict__ eW1, const float* __restrict__ eb1,
                               const float* __restrict__ eW2, const float* __restrict__ eb2,
                               const int* __restrict__ ge)
{
    int i = blockIdx.x * blockDim.x + threadIdx.x;
    if (i < GMAX * 2) g_seg[i] = 0.f;
    else if (i < GMAX * 3) g_cnt[i - GMAX * 2] = 0.f;
    if (i == 0) g_ctr = 0;
    if (i >= N) return;

    float x[16];
    for (int k = 0; k < 16; k++) x[k] = node_feat[i * 16 + k];
    float o0 = nb2[0], o1 = nb2[1];
    for (int j = 0; j < 128; j++) {
        float h = nb1[j];
        for (int k = 0; k < 16; k++) h = fmaf(x[k], nW1[k * 128 + j], h);
        h = leaky(h);
        o0 = fmaf(h, nW2[j * 2 + 0], o0);
        o1 = fmaf(h, nW2[j * 2 + 1], o1);
    }
    g_node_f[i * 2 + 0] = tanhf(o0) * PI_F;
    g_node_f[i * 2 + 1] = tanhf(o1) * PI_F;

    int eidx = ge[i * 3];
    float eAv = 0.f, eBv = 0.f;
    if (eidx >= 0) {
        float y[8];
        for (int k = 0; k < 8; k++) y[k] = edge_attr[eidx * 8 + k];
        float p0 = eb2[0], p1 = eb2[1];
        for (int j = 0; j < 128; j++) {
            float h = eb1[j];
            for (int k = 0; k < 8; k++) h = fmaf(y[k], eW1[k * 128 + j], h);
            h = leaky(h);
            p0 = fmaf(h, eW2[j * 2 + 0], p0);
            p1 = fmaf(h, eW2[j * 2 + 1], p1);
        }
        eAv = tanhf(p0) * PI_F;
        eBv = tanhf(p1) * PI_F;
    }
    g_eAB[i * 2 + 0] = eAv;
    g_eAB[i * 2 + 1] = eBv;
}

__global__ void k2_legacy(int N, const float* __restrict__ theta,
                          const float* __restrict__ uW1, const float* __restrict__ ub1,
                          const float* __restrict__ uW2, const float* __restrict__ ub2,
                          const int* __restrict__ gn)
{
    int i = blockIdx.x * blockDim.x + threadIdx.x;
    if (i >= N) return;

    int i0 = gn[i * 4 + 0], i1 = gn[i * 4 + 1];
    int i0c = max(i0, 0), i1c = max(i1, 0);
    float nf0u = g_node_f[i0c * 2 + 0];
    float nf1u = g_node_f[i0c * 2 + 1];
    float nA0 = (i0 >= 0) ? nf0u : 0.f;
    float nA1 = (i0 >= 0) ? nf1u : 0.f;
    float nB0 = (i1 >= 0) ? g_node_f[i1c * 2 + 0] : 0.f;
    float nB1 = (i1 >= 0) ? g_node_f[i1c * 2 + 1] : 0.f;
    float eA = g_eAB[i * 2 + 0], eB = g_eAB[i * 2 + 1];

    float re[32], im[32];
    for (int m = 0; m < 32; m++) { re[m] = 0.f; im[m] = 0.f; }
    re[0] = 1.f;
    float angsA[3] = {eA, nA0, nB0};
    float angsB[3] = {eB, nA1, nB1};
    int bits[3] = {1, 2, 4};
    for (int q = 0; q < 3; q++) {
        float c, s; sincosf(0.5f * angsA[q], &s, &c);
        int B = bits[q];
        for (int m = 0; m < 32; m++) if (!(m & B)) {
            int h = m | B;
            float r0 = re[m], i0v = im[m], r1 = re[h], i1v = im[h];
            re[m] = c*r0 - s*r1; im[m] = c*i0v - s*i1v;
            re[h] = s*r0 + c*r1; im[h] = s*i0v + c*i1v;
        }
        sincosf(0.5f * angsB[q], &s, &c);
        for (int m = 0; m < 32; m++) {
            float r = re[m], ii = im[m];
            if (m & B) { re[m] = c*r - s*ii; im[m] = c*ii + s*r; }
            else       { re[m] = c*r + s*ii; im[m] = c*ii - s*r; }
        }
    }
    {
        float c, s; sincosf(0.5f * nB0, &s, &c);
        for (int m = 0; m < 32; m++) if ((m & 4) && !(m & 8)) {
            int h = m | 8;
            float r0 = re[m], i0v = im[m], r1 = re[h], i1v = im[h];
            re[m] = c*r0 + s*i1v; im[m] = c*i0v - s*r1;
            re[h] = c*r1 + s*i0v; im[h] = c*i1v - s*r0;
        }
        sincosf(0.5f * eA, &s, &c);
        for (int m = 0; m < 32; m++) if ((m & 1) && !(m & 8)) {
            int h = m | 8;
            float r0 = re[m], i0v = im[m], r1 = re[h], i1v = im[h];
            re[m] = c*r0 - s*r1; im[m] = c*i0v - s*i1v;
            re[h] = s*r0 + c*r1; im[h] = s*i0v + c*i1v;
        }
        sincosf(0.5f * nB1, &s, &c);
        for (int m = 0; m < 32; m++) if (m & 4) {
            float r = re[m], ii = im[m];
            if (m & 16) { re[m] = c*r - s*ii; im[m] = c*ii + s*r; }
            else        { re[m] = c*r + s*ii; im[m] = c*ii - s*r; }
        }
        sincosf(0.5f * eB, &s, &c);
        for (int m = 0; m < 32; m++) if ((m & 1) && !(m & 16)) {
            int h = m | 16;
            float r0 = re[m], i0v = im[m], r1 = re[h], i1v = im[h];
            re[m] = c*r0 - s*r1; im[m] = c*i0v - s*i1v;
            re[h] = s*r0 + c*r1; im[h] = s*i0v + c*i1v;
        }
    }
    int qb[3][3] = {{1, 4, 8}, {8, 4, 16}, {2, 8, 16}};
    for (int b = 0; b < 3; b++) {
        for (int qq = 0; qq < 3; qq++) {
            int B = qb[b][qq];
            for (int gset = 0; gset < 3; gset++) {
                float c, s; sincosf(0.5f * theta[9*b + 3*qq + gset], &s, &c);
                if (gset == 0) {
                    for (int m = 0; m < 32; m++) if (!(m & B)) {
                        int h = m | B;
                        float r0 = re[m], i0v = im[m], r1 = re[h], i1v = im[h];
                        re[m] = c*r0 + s*i1v; im[m] = c*i0v - s*r1;
                        re[h] = c*r1 + s*i0v; im[h] = c*i1v - s*r0;
                    }
                } else if (gset == 1) {
                    for (int m = 0; m < 32; m++) if (!(m & B)) {
                        int h = m | B;
                        float r0 = re[m], i0v = im[m], r1 = re[h], i1v = im[h];
                        re[m] = c*r0 - s*r1; im[m] = c*i0v - s*i1v;
                        re[h] = s*r0 + c*r1; im[h] = s*i0v + c*i1v;
                    }
                } else {
                    for (int m = 0; m < 32; m++) {
                        float r = re[m], ii = im[m];
                        if (m & B) { re[m] = c*r - s*ii; im[m] = c*ii + s*r; }
                        else       { re[m] = c*r + s*ii; im[m] = c*ii - s*r; }
                    }
                }
            }
        }
        for (int e = 0; e < 3; e++) {
            int B1 = qb[b][e], B2 = qb[b][(e + 1) % 3];
            for (int m = 0; m < 32; m++) if ((m & B1) && (m & B2)) { re[m] = -re[m]; im[m] = -im[m]; }
        }
    }
    float ex = 0.f;
    for (int m = 0; m < 32; m++) ex += re[m]*re[m ^ 2] + im[m]*im[m ^ 2];

    float u0 = ub2[0], u1 = ub2[1];
    for (int j = 0; j < 128; j++) {
        float h = ub1[j];
        h = fmaf(nf0u, uW1[j], h);
        h = fmaf(nf1u, uW1[128 + j], h);
        h = fmaf(ex,   uW1[256 + j], h);
        h = leaky(h);
        u0 = fmaf(h, uW2[j * 2 + 0], u0);
        u1 = fmaf(h, uW2[j * 2 + 1], u1);
    }
    g_upd[i * 2 + 0] = u0;
    g_upd[i * 2 + 1] = u1;
}

__global__ void k2_scatter(int N, const int* __restrict__ gn)
{
    int i = blockIdx.x * blockDim.x + threadIdx.x;
    if (i >= N) return;
    int t = max(gn[i * 4], 0);
    atomicAdd(&g_node_f[t * 2 + 0], g_upd[i * 2 + 0]);
    atomicAdd(&g_node_f[t * 2 + 1], g_upd[i * 2 + 1]);
}

__global__ void k_seg(int N, const int* __restrict__ batch)
{
    int i = blockIdx.x * blockDim.x + threadIdx.x;
    if (i >= N) return;
    int g = batch[i];
    atomicAdd(&g_seg[g * 2 + 0], g_node_f[i * 2 + 0]);
    atomicAdd(&g_seg[g * 2 + 1], g_node_f[i * 2 + 1]);
    atomicAdd(&g_cnt[g], 1.f);
}

__global__ void k3_head(int G,
                        const float* __restrict__ hW1, const float* __restrict__ hb1,
                        const float* __restrict__ hW2, const float* __restrict__ hb2,
                        float* __restrict__ out)
{
    int g = blockIdx.x * blockDim.x + threadIdx.x;
    if (g >= G) return;
    float c = g_cnt[g];
    float inv = (c > 0.f) ? (1.f / c) : 0.f;
    float e0 = g_seg[g * 2 + 0] * inv;
    float e1 = g_seg[g * 2 + 1] * inv;
    float h0 = leaky(e0 * hW1[0] + e1 * hW1[2] + hb1[0]);
    float h1 = leaky(e0 * hW1[1] + e1 * hW1[3] + hb1[1]);
    out[g * 2 + 0] = h0 * hW2[0] + h1 * hW2[2] + hb2[0];
    out[g * 2 + 1] = h0 * hW2[1] + h1 * hW2[3] + hb2[1];
}

extern "C" void kernel_launch(void* const* d_in, const int* in_sizes, int n_in,
                              void* d_out, int out_size)
{
    const float* node_feat = (const float*)d_in[0];
    const float* edge_attr = (const float*)d_in[1];
    const float* nW1 = (const float*)d_in[2];
    const float* nb1 = (const float*)d_in[3];
    const float* nW2 = (const float*)d_in[4];
    const float* nb2 = (const float*)d_in[5];
    const float* eW1 = (const float*)d_in[6];
    const float* eb1 = (const float*)d_in[7];
    const float* eW2 = (const float*)d_in[8];
    const float* eb2 = (const float*)d_in[9];
    const float* theta = (const float*)d_in[10];
    const float* uW1 = (const float*)d_in[11];
    const float* ub1 = (const float*)d_in[12];
    const float* uW2 = (const float*)d_in[13];
    const float* ub2 = (const float*)d_in[14];
    const float* hW1 = (const float*)d_in[15];
    const float* hb1 = (const float*)d_in[16];
    const float* hW2 = (const float*)d_in[17];
    const float* hb2 = (const float*)d_in[18];
    const int* gn = (const int*)d_in[19];
    const int* ge = (const int*)d_in[20];
    const int* batch = (const int*)d_in[21];

    int N = in_sizes[0] / 16;
    int H = in_sizes[10] / 27;
    int G = out_size / 2;

    if (H == 1) {
        // k1: 4 rows/warp, 16 rows/block (R14-optimal)
        int k1blocks = (N + 15) / 16;
        k1_feat<<<k1blocks, 128>>>(node_feat, N, edge_attr, nW1, nb1, nW2, nb2,
                                   eW1, eb1, eW2, eb2, ge);

        // k2 with PDL: 16 threads/row, 8 rows/block (R14-optimal)
        int k2blocks = (N + 7) / 8;
        cudaLaunchConfig_t cfg = {};
        cfg.gridDim = dim3(k2blocks, 1, 1);
        cfg.blockDim = dim3(128, 1, 1);
        cfg.dynamicSmemBytes = 0;
        cfg.stream = 0;
        cudaLaunchAttribute attrs[1];
        attrs[0].id = cudaLaunchAttributeProgrammaticStreamSerialization;
        attrs[0].val.programmaticStreamSerializationAllowed = 1;
        cfg.attrs = attrs;
        cfg.numAttrs = 1;
        cudaError_t err = cudaLaunchKernelEx(&cfg, k2_pqc,
                                             N, 1, G, theta, uW1, ub1, uW2, ub2,
                                             gn, batch, hW1, hb1, hW2, hb2,
                                             (float*)d_out);
        if (err != cudaSuccess) {
            k2_pqc<<<k2blocks, 128>>>(N, 1, G, theta, uW1, ub1, uW2, ub2,
                                      gn, batch, hW1, hb1, hW2, hb2,
                                      (float*)d_out);
        }
    } else {
        const int T = 128;
        int nbs = (N + T - 1) / T;
        k1_feat_legacy<<<nbs, T>>>(node_feat, N, edge_attr, nW1, nb1, nW2, nb2,
                                   eW1, eb1, eW2, eb2, ge);
        for (int h = 0; h < H; h++) {
            k2_legacy<<<nbs, T>>>(N, theta + 27 * h,
                                  uW1 + 384 * h, ub1 + 128 * h,
                                  uW2 + 256 * h, ub2 + 2 * h, gn);
            k2_scatter<<<nbs, T>>>(N, gn);
        }
        k_seg<<<nbs, T>>>(N, batch);
        k3_head<<<(G + 127) / 128, 128>>>(G, hW1, hb1, hW2, hb2, (float*)d_out);
    }
}